// round 1
// baseline (speedup 1.0000x reference)
#include <cuda_runtime.h>
#include <math.h>

#define H      2048
#define NH     32
#define NKV    8
#define HD     64
#define GROUPS 4
#define FF     5632
#define BATCH  2
#define SEQ    2048
#define M_TOK  (BATCH*SEQ)

#define ATTN_SMEM (4*64*68*4)

// ---------------- scratch (device globals: allocation-guard safe) ----------------
__device__ float g_xn[M_TOK*H];        // rmsnorm output (reused for both norms)
__device__ float g_q[M_TOK*H];         // Q after proj/rope; attention writes output in-place here
__device__ float g_k[M_TOK*NKV*HD];
__device__ float g_v[M_TOK*NKV*HD];
__device__ float g_hidden[M_TOK*H];    // residual after o-proj
__device__ float g_gate[M_TOK*FF];     // gate proj, then silu(gate)*up in-place

// ---------------- RMSNorm ----------------
__global__ void rmsnorm_kernel(const float* __restrict__ x, const float* __restrict__ w,
                               float* __restrict__ y) {
    int row = blockIdx.x;
    const float4* xr = (const float4*)(x + (size_t)row * H);
    const float4* wv = (const float4*)w;
    float4* yr = (float4*)(y + (size_t)row * H);
    int tid = threadIdx.x;
    float4 a = xr[tid];
    float4 b = xr[tid + 256];
    float ss = a.x*a.x + a.y*a.y + a.z*a.z + a.w*a.w
             + b.x*b.x + b.y*b.y + b.z*b.z + b.w*b.w;
    #pragma unroll
    for (int o = 16; o; o >>= 1) ss += __shfl_xor_sync(0xffffffffu, ss, o);
    __shared__ float ws[8];
    if ((tid & 31) == 0) ws[tid >> 5] = ss;
    __syncthreads();
    float tot = ws[0]+ws[1]+ws[2]+ws[3]+ws[4]+ws[5]+ws[6]+ws[7];
    float r = rsqrtf(tot * (1.0f / (float)H) + 1e-5f);
    float4 w0 = wv[tid], w1 = wv[tid + 256];
    float4 o0, o1;
    o0.x = a.x*r*w0.x; o0.y = a.y*r*w0.y; o0.z = a.z*r*w0.z; o0.w = a.w*r*w0.w;
    o1.x = b.x*r*w1.x; o1.y = b.y*r*w1.y; o1.z = b.z*r*w1.z; o1.w = b.w*r*w1.w;
    yr[tid] = o0;
    yr[tid + 256] = o1;
}

// ---------------- GEMM with binarized weights ----------------
// C[M,N] = A[M,K] @ (aa*clip(kk*W,-1,1))[N,K]^T   (+ epilogue)
// MODE 0: store. MODE 1: store acc + X. MODE 2: store silu(X)*acc (X may alias C).
template<int MODE>
__global__ void __launch_bounds__(256, 2) gemm_binlin(
    const float* __restrict__ A, const float* __restrict__ W,
    const float* X, float* C,
    int N, int K, const float* __restrict__ kkp, const float* __restrict__ aap)
{
    __shared__ float As[8][128];
    __shared__ float Bs[8][128];
    const float kk = kkp[0];
    const float aa = aap[0];

    int bm = blockIdx.y << 7;
    int bn = blockIdx.x << 7;
    int tid = threadIdx.x;

    int lrow = tid >> 1;          // 0..127
    int lcol = (tid & 1) << 2;    // 0 or 4
    int tr = (tid >> 4) << 3;     // thread row base in tile
    int tc = (tid & 15) << 3;     // thread col base in tile

    const float* Aptr = A + (size_t)(bm + lrow) * K + lcol;
    const float* Wptr = W + (size_t)(bn + lrow) * K + lcol;

    float acc[8][8];
    #pragma unroll
    for (int i = 0; i < 8; i++)
        #pragma unroll
        for (int j = 0; j < 8; j++) acc[i][j] = 0.0f;

    for (int kb = 0; kb < K; kb += 8) {
        float4 av = *(const float4*)(Aptr + kb);
        float4 wv = *(const float4*)(Wptr + kb);
        As[lcol + 0][lrow] = av.x;
        As[lcol + 1][lrow] = av.y;
        As[lcol + 2][lrow] = av.z;
        As[lcol + 3][lrow] = av.w;
        Bs[lcol + 0][lrow] = aa * fminf(fmaxf(kk * wv.x, -1.0f), 1.0f);
        Bs[lcol + 1][lrow] = aa * fminf(fmaxf(kk * wv.y, -1.0f), 1.0f);
        Bs[lcol + 2][lrow] = aa * fminf(fmaxf(kk * wv.z, -1.0f), 1.0f);
        Bs[lcol + 3][lrow] = aa * fminf(fmaxf(kk * wv.w, -1.0f), 1.0f);
        __syncthreads();
        #pragma unroll
        for (int k = 0; k < 8; k++) {
            float ar[8], br[8];
            *(float4*)&ar[0] = *(const float4*)&As[k][tr];
            *(float4*)&ar[4] = *(const float4*)&As[k][tr + 4];
            *(float4*)&br[0] = *(const float4*)&Bs[k][tc];
            *(float4*)&br[4] = *(const float4*)&Bs[k][tc + 4];
            #pragma unroll
            for (int i = 0; i < 8; i++)
                #pragma unroll
                for (int j = 0; j < 8; j++)
                    acc[i][j] += ar[i] * br[j];
        }
        __syncthreads();
    }

    #pragma unroll
    for (int i = 0; i < 8; i++) {
        size_t off = (size_t)(bm + tr + i) * N + bn + tc;
        #pragma unroll
        for (int j4 = 0; j4 < 8; j4 += 4) {
            float4 r;
            float v0 = acc[i][j4 + 0];
            float v1 = acc[i][j4 + 1];
            float v2 = acc[i][j4 + 2];
            float v3 = acc[i][j4 + 3];
            if (MODE == 1) {
                const float4 xr = *(const float4*)(X + off + j4);
                v0 += xr.x; v1 += xr.y; v2 += xr.z; v3 += xr.w;
            } else if (MODE == 2) {
                const float4 gr = *(const float4*)(X + off + j4);
                v0 *= gr.x / (1.0f + expf(-gr.x));
                v1 *= gr.y / (1.0f + expf(-gr.y));
                v2 *= gr.z / (1.0f + expf(-gr.z));
                v3 *= gr.w / (1.0f + expf(-gr.w));
            }
            r.x = v0; r.y = v1; r.z = v2; r.w = v3;
            *(float4*)(C + off + j4) = r;
        }
    }
}

// ---------------- RoPE (in-place on g_q and g_k) ----------------
__global__ void rope_kernel(const int* __restrict__ pos_ids) {
    int gid = blockIdx.x * blockDim.x + threadIdx.x;
    int d = gid & 31;
    int slot = gid >> 5;
    int head = slot % (NH + NKV);
    int tok = slot / (NH + NKV);
    if (tok >= M_TOK) return;
    float p = (float)pos_ids[tok];
    float inv = powf(10000.0f, -(float)d * (1.0f / 32.0f));
    float ang = p * inv;
    float s, c;
    sincosf(ang, &s, &c);
    float* base;
    if (head < NH) base = g_q + (((size_t)tok * NH + head) << 6);
    else           base = g_k + (((size_t)tok * NKV + (head - NH)) << 6);
    float x1 = base[d];
    float x2 = base[d + 32];
    base[d]      = x1 * c - x2 * s;
    base[d + 32] = x2 * c + x1 * s;
}

// ---------------- Flash attention (causal, GQA), output in-place into g_q ----------------
__global__ void __launch_bounds__(256, 1) attn_kernel() {
    extern __shared__ float sm[];
    float* Qt  = sm;                // [64][68] (q,d), pre-scaled by 1/8
    float* KtT = sm + 64 * 68;      // [64][68] (d,kc) transposed
    float* Vt  = sm + 2 * 64 * 68;  // [64][68] (kc,d)
    float* St  = sm + 3 * 64 * 68;  // [64][68] (q,kc) scores -> probs

    int qt = blockIdx.x, h = blockIdx.y, b = blockIdx.z;
    int kh = h >> 2;   // GQA: 4 q heads per kv head
    int tid = threadIdx.x;

    // load Q tile (scaled by 1/sqrt(HD)=1/8)
    for (int i = tid; i < 1024; i += 256) {
        int r = i >> 4, c4 = (i & 15) << 2;
        const float* src = g_q + (((size_t)(b * SEQ + (qt << 6) + r) * NH + h) << 6) + c4;
        float4 qv = *(const float4*)src;
        float* dst = &Qt[r * 68 + c4];
        dst[0] = qv.x * 0.125f; dst[1] = qv.y * 0.125f;
        dst[2] = qv.z * 0.125f; dst[3] = qv.w * 0.125f;
    }

    int qr = tid >> 2, qc = tid & 3;     // softmax/PV mapping: row qr, dims qc*16..+16
    int pi = tid >> 4, pj = tid & 15;    // score mapping: 4x4 patch
    int qr0 = pi << 2, kc0 = pj << 2;

    float acc[16];
    #pragma unroll
    for (int d = 0; d < 16; d++) acc[d] = 0.0f;
    float mrow = -INFINITY, lrow = 0.0f;

    for (int kt = 0; kt <= qt; kt++) {
        __syncthreads();  // previous-tile phase C done before K/V overwrite
        int tokbase = b * SEQ + (kt << 6);
        // K transposed
        for (int i = tid; i < 1024; i += 256) {
            int r = i & 63, c4 = (i >> 6) << 2;
            const float* src = g_k + (((size_t)(tokbase + r) * NKV + kh) << 6) + c4;
            float4 kv = *(const float4*)src;
            KtT[(c4 + 0) * 68 + r] = kv.x;
            KtT[(c4 + 1) * 68 + r] = kv.y;
            KtT[(c4 + 2) * 68 + r] = kv.z;
            KtT[(c4 + 3) * 68 + r] = kv.w;
        }
        // V row-major
        for (int i = tid; i < 1024; i += 256) {
            int r = i >> 4, c4 = (i & 15) << 2;
            const float* src = g_v + (((size_t)(tokbase + r) * NKV + kh) << 6) + c4;
            *(float4*)&Vt[r * 68 + c4] = *(const float4*)src;
        }
        __syncthreads();

        // phase A: S = (Q/8) K^T  (4x4 patch per thread)
        float sacc[4][4];
        #pragma unroll
        for (int i = 0; i < 4; i++)
            #pragma unroll
            for (int j = 0; j < 4; j++) sacc[i][j] = 0.0f;
        #pragma unroll
        for (int d4 = 0; d4 < 64; d4 += 4) {
            float aq[4][4], bk[4][4];
            #pragma unroll
            for (int i = 0; i < 4; i++)
                *(float4*)aq[i] = *(const float4*)&Qt[(qr0 + i) * 68 + d4];
            #pragma unroll
            for (int dd = 0; dd < 4; dd++)
                *(float4*)bk[dd] = *(const float4*)&KtT[(d4 + dd) * 68 + kc0];
            #pragma unroll
            for (int i = 0; i < 4; i++)
                #pragma unroll
                for (int dd = 0; dd < 4; dd++)
                    #pragma unroll
                    for (int j = 0; j < 4; j++)
                        sacc[i][j] += aq[i][dd] * bk[dd][j];
        }
        // causal mask on diagonal tile, store scores
        bool diag = (kt == qt);
        #pragma unroll
        for (int i = 0; i < 4; i++) {
            int qg = (qt << 6) + qr0 + i;
            float4 r;
            float v0 = sacc[i][0], v1 = sacc[i][1], v2 = sacc[i][2], v3 = sacc[i][3];
            if (diag) {
                int kg = (kt << 6) + kc0;
                if (kg + 0 > qg) v0 = -INFINITY;
                if (kg + 1 > qg) v1 = -INFINITY;
                if (kg + 2 > qg) v2 = -INFINITY;
                if (kg + 3 > qg) v3 = -INFINITY;
            }
            r.x = v0; r.y = v1; r.z = v2; r.w = v3;
            *(float4*)&St[(qr0 + i) * 68 + kc0] = r;
        }
        __syncthreads();

        // phase B: online softmax (4 lanes per row)
        float* srow = &St[qr * 68 + (qc << 4)];
        float tmax = -INFINITY;
        #pragma unroll
        for (int j = 0; j < 16; j++) tmax = fmaxf(tmax, srow[j]);
        tmax = fmaxf(tmax, __shfl_xor_sync(0xffffffffu, tmax, 1));
        tmax = fmaxf(tmax, __shfl_xor_sync(0xffffffffu, tmax, 2));
        float mnew = fmaxf(mrow, tmax);
        float corr = __expf(mrow - mnew);
        float psum = 0.0f;
        #pragma unroll
        for (int j = 0; j < 16; j++) {
            float pv = __expf(srow[j] - mnew);
            srow[j] = pv;
            psum += pv;
        }
        psum += __shfl_xor_sync(0xffffffffu, psum, 1);
        psum += __shfl_xor_sync(0xffffffffu, psum, 2);
        lrow = lrow * corr + psum;
        mrow = mnew;
        #pragma unroll
        for (int d = 0; d < 16; d++) acc[d] *= corr;
        __syncwarp();  // sibling lanes' prob writes visible (same warp owns row qr)

        // phase C: acc += P V
        for (int kc = 0; kc < 64; kc++) {
            float pv = St[qr * 68 + kc];
            const float4 v0 = *(const float4*)&Vt[kc * 68 + (qc << 4) + 0];
            const float4 v1 = *(const float4*)&Vt[kc * 68 + (qc << 4) + 4];
            const float4 v2 = *(const float4*)&Vt[kc * 68 + (qc << 4) + 8];
            const float4 v3 = *(const float4*)&Vt[kc * 68 + (qc << 4) + 12];
            acc[0]  += pv * v0.x; acc[1]  += pv * v0.y; acc[2]  += pv * v0.z; acc[3]  += pv * v0.w;
            acc[4]  += pv * v1.x; acc[5]  += pv * v1.y; acc[6]  += pv * v1.z; acc[7]  += pv * v1.w;
            acc[8]  += pv * v2.x; acc[9]  += pv * v2.y; acc[10] += pv * v2.z; acc[11] += pv * v2.w;
            acc[12] += pv * v3.x; acc[13] += pv * v3.y; acc[14] += pv * v3.z; acc[15] += pv * v3.w;
        }
    }

    // epilogue: normalize, write back in-place over this block's Q region
    float inv_l = 1.0f / lrow;
    float* outp = g_q + (((size_t)(b * SEQ + (qt << 6) + qr) * NH + h) << 6) + (qc << 4);
    #pragma unroll
    for (int d = 0; d < 16; d += 4) {
        float4 o;
        o.x = acc[d + 0] * inv_l;
        o.y = acc[d + 1] * inv_l;
        o.z = acc[d + 2] * inv_l;
        o.w = acc[d + 3] * inv_l;
        *(float4*)&outp[d] = o;
    }
}

// ---------------- launch ----------------
extern "C" void kernel_launch(void* const* d_in, const int* in_sizes, int n_in,
                              void* d_out, int out_size) {
    (void)in_sizes; (void)n_in; (void)out_size;
    const float* hs     = (const float*)d_in[0];
    const int*   pos    = (const int*)d_in[2];
    const float* q_w    = (const float*)d_in[3];
    const float* k_w    = (const float*)d_in[4];
    const float* v_w    = (const float*)d_in[5];
    const float* o_w    = (const float*)d_in[6];
    const float* gate_w = (const float*)d_in[7];
    const float* up_w   = (const float*)d_in[8];
    const float* down_w = (const float*)d_in[9];
    const float* ln1    = (const float*)d_in[10];
    const float* ln2    = (const float*)d_in[11];
    const float* kkp    = (const float*)d_in[12];
    const float* aap    = (const float*)d_in[13];
    float* out = (float*)d_out;

    float *xn, *q, *k, *v, *hid, *gate;
    cudaGetSymbolAddress((void**)&xn,   g_xn);
    cudaGetSymbolAddress((void**)&q,    g_q);
    cudaGetSymbolAddress((void**)&k,    g_k);
    cudaGetSymbolAddress((void**)&v,    g_v);
    cudaGetSymbolAddress((void**)&hid,  g_hidden);
    cudaGetSymbolAddress((void**)&gate, g_gate);

    cudaFuncSetAttribute(attn_kernel, cudaFuncAttributeMaxDynamicSharedMemorySize, ATTN_SMEM);

    dim3 blk(256);

    // 1) rmsnorm 1
    rmsnorm_kernel<<<M_TOK, blk>>>(hs, ln1, xn);
    // 2) q/k/v projections
    gemm_binlin<0><<<dim3(H / 128, M_TOK / 128), blk>>>(xn, q_w, nullptr, q, H, H, kkp, aap);
    gemm_binlin<0><<<dim3((NKV * HD) / 128, M_TOK / 128), blk>>>(xn, k_w, nullptr, k, NKV * HD, H, kkp, aap);
    gemm_binlin<0><<<dim3((NKV * HD) / 128, M_TOK / 128), blk>>>(xn, v_w, nullptr, v, NKV * HD, H, kkp, aap);
    // 3) rope on q and k
    rope_kernel<<<(M_TOK * (NH + NKV) * 32) / 256, blk>>>(pos);
    // 4) attention (writes into g_q)
    attn_kernel<<<dim3(SEQ / 64, NH, BATCH), blk, ATTN_SMEM>>>();
    // 5) o-proj + residual
    gemm_binlin<1><<<dim3(H / 128, M_TOK / 128), blk>>>(q, o_w, hs, hid, H, H, kkp, aap);
    // 6) rmsnorm 2
    rmsnorm_kernel<<<M_TOK, blk>>>(hid, ln2, xn);
    // 7) gate proj
    gemm_binlin<0><<<dim3(FF / 128, M_TOK / 128), blk>>>(xn, gate_w, nullptr, gate, FF, H, kkp, aap);
    // 8) up proj fused with silu(gate)*up  (in-place into gate buffer)
    gemm_binlin<2><<<dim3(FF / 128, M_TOK / 128), blk>>>(xn, up_w, gate, gate, FF, H, kkp, aap);
    // 9) down proj + residual -> output
    gemm_binlin<1><<<dim3(H / 128, M_TOK / 128), blk>>>(gate, down_w, hid, out, H, FF, kkp, aap);
}